// round 16
// baseline (speedup 1.0000x reference)
#include <cuda_runtime.h>
#include <cuda_bf16.h>

#define N_FEAT 1024
#define RANK 4
#define SCALING 0.25f
#define TPB 256
#define ROWS_PER_CTA 16     // 8 warps x 2 rows
#define ROWS_PER_WARP 2
#define NCHUNK 8            // 1024 cols / (32 lanes * 4 floats)

__global__ __launch_bounds__(TPB) void lora_fused_kernel(
    const float* __restrict__ x,      // [M, 1024]
    const float* __restrict__ A,      // [4, 1024]
    const float* __restrict__ B,      // [1024, 4]
    float* __restrict__ out)          // [M, 1024]
{
    const int t    = threadIdx.x;
    const int lane = t & 31;
    const int warp = t >> 5;
    const int row0 = blockIdx.x * ROWS_PER_CTA;

    __shared__ float4 As[RANK][N_FEAT / 4];   // 16 KB, A rows as float4
    __shared__ float4 h4[ROWS_PER_CTA];       // 256 B

    // ---- stage A into smem (coalesced) ----
    {
        const float4* Av = reinterpret_cast<const float4*>(A);
        #pragma unroll
        for (int r = 0; r < RANK; ++r)
            As[r][t] = Av[r * (N_FEAT / 4) + t];
    }
    __syncthreads();

    // ---- contraction: each warp owns 2 rows, accumulates over 8 chunks ----
    const int myrow = row0 + warp * ROWS_PER_WARP;
    const float4* x0 = reinterpret_cast<const float4*>(x + (size_t)myrow * N_FEAT);
    const float4* x1 = x0 + (N_FEAT / 4);

    float q00 = 0.f, q01 = 0.f, q02 = 0.f, q03 = 0.f;   // row 0, ranks 0-3
    float q10 = 0.f, q11 = 0.f, q12 = 0.f, q13 = 0.f;   // row 1, ranks 0-3

    #pragma unroll
    for (int c = 0; c < NCHUNK; ++c) {
        const int idx = c * 32 + lane;
        const float4 xv0 = __ldcs(&x0[idx]);            // streaming reads
        const float4 xv1 = __ldcs(&x1[idx]);
        const float4 a0 = As[0][idx];
        const float4 a1 = As[1][idx];
        const float4 a2 = As[2][idx];
        const float4 a3 = As[3][idx];

        q00 += xv0.x * a0.x + xv0.y * a0.y + xv0.z * a0.z + xv0.w * a0.w;
        q01 += xv0.x * a1.x + xv0.y * a1.y + xv0.z * a1.z + xv0.w * a1.w;
        q02 += xv0.x * a2.x + xv0.y * a2.y + xv0.z * a2.z + xv0.w * a2.w;
        q03 += xv0.x * a3.x + xv0.y * a3.y + xv0.z * a3.z + xv0.w * a3.w;
        q10 += xv1.x * a0.x + xv1.y * a0.y + xv1.z * a0.z + xv1.w * a0.w;
        q11 += xv1.x * a1.x + xv1.y * a1.y + xv1.z * a1.z + xv1.w * a1.w;
        q12 += xv1.x * a2.x + xv1.y * a2.y + xv1.z * a2.z + xv1.w * a2.w;
        q13 += xv1.x * a3.x + xv1.y * a3.y + xv1.z * a3.z + xv1.w * a3.w;
    }

    // ---- one 6-shfl rank-interleaved reduction per owned row ----
    #pragma unroll
    for (int rr = 0; rr < ROWS_PER_WARP; ++rr) {
        float p0 = rr ? q10 : q00;
        float p1 = rr ? q11 : q01;
        float p2 = rr ? q12 : q02;
        float p3 = rr ? q13 : q03;

        float va = (lane & 1) ? p1 : p0;
        float vb = (lane & 1) ? p0 : p1;
        float vc = (lane & 1) ? p3 : p2;
        float vd = (lane & 1) ? p2 : p3;
        va += __shfl_xor_sync(0xFFFFFFFFu, vb, 1);
        vc += __shfl_xor_sync(0xFFFFFFFFu, vd, 1);
        float ve = (lane & 2) ? vc : va;
        float vf = (lane & 2) ? va : vc;
        ve += __shfl_xor_sync(0xFFFFFFFFu, vf, 2);
        ve += __shfl_xor_sync(0xFFFFFFFFu, ve, 4);
        ve += __shfl_xor_sync(0xFFFFFFFFu, ve, 8);
        ve += __shfl_xor_sync(0xFFFFFFFFu, ve, 16);

        // lane L owns rank (L & 3); lanes 0-3 carry the 4 rank sums
        if (lane < RANK)
            reinterpret_cast<float*>(&h4[warp * ROWS_PER_WARP + rr])[lane] = ve * SCALING;
    }
    __syncthreads();

    // ---- expansion: B in registers (loaded after barrier), 16 output rows ----
    const float4* Bv = reinterpret_cast<const float4*>(B);
    const float4 b0 = Bv[4 * t + 0];
    const float4 b1 = Bv[4 * t + 1];
    const float4 b2 = Bv[4 * t + 2];
    const float4 b3 = Bv[4 * t + 3];

    float4* outr = reinterpret_cast<float4*>(out + (size_t)row0 * N_FEAT) + t;
    #pragma unroll
    for (int r = 0; r < ROWS_PER_CTA; ++r) {
        const float4 h = h4[r];   // broadcast LDS.128
        float4 o;
        o.x = h.x * b0.x + h.y * b0.y + h.z * b0.z + h.w * b0.w;
        o.y = h.x * b1.x + h.y * b1.y + h.z * b1.z + h.w * b1.w;
        o.z = h.x * b2.x + h.y * b2.y + h.z * b2.z + h.w * b2.w;
        o.w = h.x * b3.x + h.y * b3.y + h.z * b3.z + h.w * b3.w;
        __stcs(&outr[(size_t)r * (N_FEAT / 4)], o);     // streaming stores
    }
}

extern "C" void kernel_launch(void* const* d_in, const int* in_sizes, int n_in,
                              void* d_out, int out_size)
{
    const float* x = (const float*)d_in[0];
    const float* A = (const float*)d_in[1];
    const float* B = (const float*)d_in[2];
    float* out = (float*)d_out;

    const int rows = in_sizes[0] / N_FEAT;   // 32768
    lora_fused_kernel<<<rows / ROWS_PER_CTA, TPB>>>(x, A, B, out);
}